// round 15
// baseline (speedup 1.0000x reference)
#include <cuda_runtime.h>
#include <cuda_bf16.h>
#include <math.h>
#include <stdint.h>

#define T_TOK   2048
#define H_DIM   1024
#define N_EXP   16
#define F_DIM   1024
#define N_SLOTS 4096

// ---------------- device scratch (no allocations allowed) ----------------
__device__ __nv_bfloat16 g_xhi[(size_t)T_TOK * H_DIM];
__device__ __nv_bfloat16 g_xlo[(size_t)T_TOK * H_DIM];
__device__ __nv_bfloat16 g_guh[(size_t)N_EXP * H_DIM * 2048];
__device__ __nv_bfloat16 g_gul[(size_t)N_EXP * H_DIM * 2048];
__device__ __nv_bfloat16 g_dnh[(size_t)N_EXP * F_DIM * H_DIM];
__device__ __nv_bfloat16 g_dnl[(size_t)N_EXP * F_DIM * H_DIM];
__device__ __nv_bfloat16 g_hhi[(size_t)N_SLOTS * F_DIM];
__device__ __nv_bfloat16 g_hlo[(size_t)N_SLOTS * F_DIM];
__device__ float g_eo[(size_t)N_SLOTS * H_DIM];
__device__ int   g_cnt[N_EXP];
__device__ int   g_slots[N_EXP * N_SLOTS];
__device__ float g_w[N_SLOTS];

// ---------------- helpers ----------------
__device__ __forceinline__ uint32_t smem_u32(const void* p) {
    uint32_t a;
    asm("{ .reg .u64 t; cvta.to.shared.u64 t, %1; cvt.u32.u64 %0, t; }" : "=r"(a) : "l"(p));
    return a;
}
#define SW128(o) ((o) ^ (((o) >> 3) & 0x70))
#define SW64(o)  ((o) ^ (((o) >> 3) & 0x30))

__device__ __forceinline__ uint32_t pack2(__nv_bfloat16 a, __nv_bfloat16 b) {
    return (uint32_t)__bfloat16_as_ushort(a) | ((uint32_t)__bfloat16_as_ushort(b) << 16);
}
__device__ __forceinline__ void split1(float v, __nv_bfloat16& h, __nv_bfloat16& l) {
    h = __float2bfloat16(v);
    l = __float2bfloat16(v - __bfloat162float(h));
}

__device__ __forceinline__ void cpa16(uint32_t dst, const void* src, int sz) {
    asm volatile("cp.async.cg.shared.global [%0], [%1], 16, %2;"
        :: "r"(dst), "l"(src), "r"(sz) : "memory");
}
#define CP_COMMIT() asm volatile("cp.async.commit_group;" ::: "memory")
#define CP_WAIT(n)  asm volatile("cp.async.wait_group %0;" :: "n"(n) : "memory")

__device__ __forceinline__ void ldsm4(uint32_t (&r)[4], uint32_t addr) {
    asm volatile("ldmatrix.sync.aligned.m8n8.x4.shared.b16 {%0,%1,%2,%3}, [%4];"
        : "=r"(r[0]), "=r"(r[1]), "=r"(r[2]), "=r"(r[3]) : "r"(addr));
}
__device__ __forceinline__ void ldsm4t(uint32_t (&r)[4], uint32_t addr) {
    asm volatile("ldmatrix.sync.aligned.m8n8.x4.trans.shared.b16 {%0,%1,%2,%3}, [%4];"
        : "=r"(r[0]), "=r"(r[1]), "=r"(r[2]), "=r"(r[3]) : "r"(addr));
}
__device__ __forceinline__ void mma16816(float (&d)[4], const uint32_t (&a)[4],
                                         uint32_t b0, uint32_t b1) {
    asm volatile("mma.sync.aligned.m16n8k16.row.col.f32.bf16.bf16.f32 "
        "{%0,%1,%2,%3},{%4,%5,%6,%7},{%8,%9},{%0,%1,%2,%3};"
        : "+f"(d[0]), "+f"(d[1]), "+f"(d[2]), "+f"(d[3])
        : "r"(a[0]), "r"(a[1]), "r"(a[2]), "r"(a[3]), "r"(b0), "r"(b1));
}

// ---------------- kernel: fp32 -> bf16 hi/lo plane split (vectorized 2x) ----------------
// sel==0 additionally zeroes the expert counters (block 0), replacing zero_cnt_kernel.
__global__ void convert_sel(const float4* __restrict__ src, int sel, int n8) {
    if (sel == 0 && blockIdx.x == 0 && threadIdx.x < N_EXP) g_cnt[threadIdx.x] = 0;
    int i = blockIdx.x * blockDim.x + threadIdx.x;   // uint4 (8-element) index
    if (i >= n8) return;
    uint4* hi; uint4* lo;
    if (sel == 0)      { hi = (uint4*)g_xhi; lo = (uint4*)g_xlo; }
    else if (sel == 1) { hi = (uint4*)g_guh; lo = (uint4*)g_gul; }
    else               { hi = (uint4*)g_dnh; lo = (uint4*)g_dnl; }
    float4 v0 = src[2 * i], v1 = src[2 * i + 1];
    __nv_bfloat16 h0,h1,h2,h3,h4,h5,h6,h7,l0,l1,l2,l3,l4,l5,l6,l7;
    split1(v0.x,h0,l0); split1(v0.y,h1,l1); split1(v0.z,h2,l2); split1(v0.w,h3,l3);
    split1(v1.x,h4,l4); split1(v1.y,h5,l5); split1(v1.z,h6,l6); split1(v1.w,h7,l7);
    hi[i] = make_uint4(pack2(h0,h1), pack2(h2,h3), pack2(h4,h5), pack2(h6,h7));
    lo[i] = make_uint4(pack2(l0,l1), pack2(l2,l3), pack2(l4,l5), pack2(l6,l7));
}

// ---------------- kernel: router (champion version) ----------------
__global__ void router_kernel(const float* __restrict__ x, const float* __restrict__ rw) {
    int t = blockIdx.x * blockDim.y + threadIdx.y;
    if (t >= T_TOK) return;
    int lane = threadIdx.x;
    float acc[N_EXP];
#pragma unroll
    for (int e = 0; e < N_EXP; e++) acc[e] = 0.f;
    const float* xrow = x + (size_t)t * H_DIM;
    for (int h = lane; h < H_DIM; h += 32) {
        float xv = xrow[h];
        const float4* r4 = (const float4*)(rw + (size_t)h * N_EXP);
#pragma unroll
        for (int q = 0; q < 4; q++) {
            float4 v = r4[q];
            acc[q*4+0] += xv*v.x; acc[q*4+1] += xv*v.y;
            acc[q*4+2] += xv*v.z; acc[q*4+3] += xv*v.w;
        }
    }
#pragma unroll
    for (int e = 0; e < N_EXP; e++)
#pragma unroll
        for (int off = 16; off > 0; off >>= 1)
            acc[e] += __shfl_down_sync(0xffffffffu, acc[e], off);
    if (lane == 0) {
        int i0 = -1, i1 = -1; float v0 = -INFINITY, v1 = -INFINITY;
#pragma unroll
        for (int e = 0; e < N_EXP; e++) {
            float v = acc[e];
            if (v > v0) { v1 = v0; i1 = i0; v0 = v; i0 = e; }
            else if (v > v1) { v1 = v; i1 = e; }
        }
        float w0 = 1.f / (1.f + expf(v1 - v0));
        int p0 = atomicAdd(&g_cnt[i0], 1);
        g_slots[i0 * N_SLOTS + p0] = 2*t;     g_w[2*t]   = w0;
        int p1 = atomicAdd(&g_cnt[i1], 1);
        g_slots[i1 * N_SLOTS + p1] = 2*t+1;   g_w[2*t+1] = 1.f - w0;
    }
}

// ---------------- 2-stage mainloop: 128x128 tile, K=1024, chunk 16 ----------------
__device__ __forceinline__ void stage_chunk(
    int c, uint32_t dA, uint32_t dB, const int* rows, int shift,
    const __nv_bfloat16* __restrict__ Ahi, const __nv_bfloat16* __restrict__ Alo,
    const __nv_bfloat16* __restrict__ Bhi, const __nv_bfloat16* __restrict__ Blo,
    size_t bbase, int bstride, int bnh)
{
    int tid = threadIdx.x;
#pragma unroll
    for (int it = 0; it < 2; it++) {
        int i = tid + it * 256;
        int m = i >> 2, ch = i & 3, p = ch >> 1, kq = ch & 1;
        int s = rows[m];
        const __nv_bfloat16* base = p ? Alo : Ahi;
        int sr = (s < 0) ? 0 : (s >> shift);
        const __nv_bfloat16* sp = base + ((size_t)sr * 1024 + c * 16 + kq * 8);
        cpa16(dA + SW64((uint32_t)(m * 64 + ch * 16)), sp, (s >= 0) ? 16 : 0);
    }
#pragma unroll
    for (int it = 0; it < 2; it++) {
        int i = tid + it * 256;
        int p = i >> 8, r = i & 255, nh = r >> 7, rr = r & 127, k = rr >> 3, nc = rr & 7;
        const __nv_bfloat16* base = p ? Blo : Bhi;
        const __nv_bfloat16* sp = base + (bbase + (size_t)(c * 16 + k) * bstride + nh * bnh + nc * 8);
        cpa16(dB + SW128((uint32_t)(p * 4096 + nh * 2048 + k * 128 + nc * 16)), sp, 16);
    }
}

__device__ __forceinline__ void gemm_loop(
    float (&acc)[2][8][4], char* smA, char* smB, const int* rows, int shift,
    const __nv_bfloat16* __restrict__ Ahi, const __nv_bfloat16* __restrict__ Alo,
    const __nv_bfloat16* __restrict__ Bhi, const __nv_bfloat16* __restrict__ Blo,
    size_t bbase, int bstride, int bnh)
{
    int lane = threadIdx.x & 31, wid = threadIdx.x >> 5;
    int wm = wid & 3, wn = wid >> 2;
    uint32_t aA = smem_u32(smA), aB = smem_u32(smB);

    stage_chunk(0, aA, aB, rows, shift, Ahi, Alo, Bhi, Blo, bbase, bstride, bnh);
    CP_COMMIT();

    for (int c = 0; c < 64; c++) {
        if (c < 63) {
            stage_chunk(c + 1, aA + ((c + 1) & 1) * 8192, aB + ((c + 1) & 1) * 8192,
                        rows, shift, Ahi, Alo, Bhi, Blo, bbase, bstride, bnh);
            CP_COMMIT();
            CP_WAIT(1);
        } else {
            CP_WAIT(0);
        }
        __syncthreads();
        uint32_t bA = aA + (c & 1) * 8192, bB = aB + (c & 1) * 8192;
        uint32_t ah[2][4], al[2][4], bhf[4][4], blf[4][4];
#pragma unroll
        for (int mf = 0; mf < 2; mf++) {
            int row = wm * 32 + mf * 16 + (lane & 15);
            int cb = (lane >> 4) * 16;
            ldsm4(ah[mf], bA + SW64((uint32_t)(row * 64 + cb)));
            ldsm4(al[mf], bA + SW64((uint32_t)(row * 64 + 32 + cb)));
        }
#pragma unroll
        for (int g = 0; g < 4; g++) {
            uint32_t co = wn * 2048 + (lane & 15) * 128 + (g * 16 + (lane >> 4) * 8) * 2;
            ldsm4t(bhf[g], bB + SW128(co));
            ldsm4t(blf[g], bB + SW128(4096 + co));
        }
#pragma unroll
        for (int mf = 0; mf < 2; mf++)
#pragma unroll
            for (int g = 0; g < 4; g++) {
                mma16816(acc[mf][2*g],   ah[mf], bhf[g][0], bhf[g][1]);
                mma16816(acc[mf][2*g+1], ah[mf], bhf[g][2], bhf[g][3]);
                mma16816(acc[mf][2*g],   ah[mf], blf[g][0], blf[g][1]);
                mma16816(acc[mf][2*g+1], ah[mf], blf[g][2], blf[g][3]);
                mma16816(acc[mf][2*g],   al[mf], bhf[g][0], bhf[g][1]);
                mma16816(acc[mf][2*g+1], al[mf], bhf[g][2], bhf[g][3]);
            }
        __syncthreads();
    }
}

// ---------------- kernel: gate_up GEMM + fused SiLU ----------------
// grid (32 m-tiles, 16 experts, 16 f-tiles): 64 f per tile (gate j*64.., up 1024+j*64..)
__global__ __launch_bounds__(256) void gemm1_kernel() {
    __shared__ int rows[128];
    __shared__ __align__(128) char smem_all[35328];
    int e = blockIdx.y, m0 = blockIdx.x * 128, j = blockIdx.z;
    int cnt = g_cnt[e];
    if (m0 >= cnt) return;
    int tid = threadIdx.x, lane = tid & 31, wid = tid >> 5, wm = wid & 3, wn = wid >> 2;
    if (tid < 128) rows[tid] = (m0 + tid < cnt) ? g_slots[e * N_SLOTS + m0 + tid] : -1;
    __syncthreads();

    float acc[2][8][4] = {};
    gemm_loop(acc, smem_all, smem_all + 16384, rows, 1,
              g_xhi, g_xlo, g_guh, g_gul,
              (size_t)e * H_DIM * 2048 + (size_t)j * 64, 2048, 1024);

    // epilogue: exchange up half through SMEM, fuse SiLU, write bf16 hi/lo act
    float* up_sm = (float*)smem_all;   // [128][68]
    if (wn == 1) {
#pragma unroll
        for (int mf = 0; mf < 2; mf++)
#pragma unroll
            for (int nf = 0; nf < 8; nf++) {
                int f = nf * 8 + (lane & 3) * 2;
                int m = wm * 32 + mf * 16 + (lane >> 2);
                up_sm[m * 68 + f]           = acc[mf][nf][0];
                up_sm[m * 68 + f + 1]       = acc[mf][nf][1];
                up_sm[(m + 8) * 68 + f]     = acc[mf][nf][2];
                up_sm[(m + 8) * 68 + f + 1] = acc[mf][nf][3];
            }
    }
    __syncthreads();
    if (wn == 0) {
#pragma unroll
        for (int mf = 0; mf < 2; mf++)
#pragma unroll
            for (int nf = 0; nf < 8; nf++) {
                int f = nf * 8 + (lane & 3) * 2;
                int mb = wm * 32 + mf * 16 + (lane >> 2);
#pragma unroll
                for (int h2 = 0; h2 < 2; h2++) {
                    int m = mb + h2 * 8;
                    int s = rows[m];
                    if (s < 0) continue;
                    float gg0 = acc[mf][nf][h2*2], gg1 = acc[mf][nf][h2*2+1];
                    float u0 = up_sm[m*68 + f], u1 = up_sm[m*68 + f + 1];
                    float x0 = gg0 / (1.f + expf(-gg0)) * u0;
                    float x1 = gg1 / (1.f + expf(-gg1)) * u1;
                    __nv_bfloat16 h0,h1,l0,l1;
                    split1(x0,h0,l0); split1(x1,h1,l1);
                    size_t o = (size_t)s * F_DIM + j * 64 + f;
                    *(uint32_t*)(g_hhi + o) = pack2(h0,h1);
                    *(uint32_t*)(g_hlo + o) = pack2(l0,l1);
                }
            }
    }
}

// ---------------- kernel: down GEMM (+routing weight) ----------------
// grid (32 m-tiles, 16 experts, 8 h-tiles)
__global__ __launch_bounds__(256) void gemm2_kernel() {
    __shared__ int rows[128];
    __shared__ __align__(128) char smem_all[32768];
    int e = blockIdx.y, m0 = blockIdx.x * 128, n0 = blockIdx.z * 128;
    int cnt = g_cnt[e];
    if (m0 >= cnt) return;
    int tid = threadIdx.x, lane = tid & 31, wid = tid >> 5, wm = wid & 3, wn = wid >> 2;
    if (tid < 128) rows[tid] = (m0 + tid < cnt) ? g_slots[e * N_SLOTS + m0 + tid] : -1;
    __syncthreads();

    float acc[2][8][4] = {};
    gemm_loop(acc, smem_all, smem_all + 16384, rows, 0,
              g_hhi, g_hlo, g_dnh, g_dnl,
              (size_t)e * F_DIM * H_DIM + (size_t)n0, 1024, 64);

#pragma unroll
    for (int mf = 0; mf < 2; mf++)
#pragma unroll
        for (int nf = 0; nf < 8; nf++) {
            int n = n0 + wn * 64 + nf * 8 + (lane & 3) * 2;
            int mb = wm * 32 + mf * 16 + (lane >> 2);
#pragma unroll
            for (int h2 = 0; h2 < 2; h2++) {
                int m = mb + h2 * 8;
                int s = rows[m];
                if (s < 0) continue;
                float w = g_w[s];
                *(float2*)(g_eo + (size_t)s * H_DIM + n) =
                    make_float2(w * acc[mf][nf][h2*2], w * acc[mf][nf][h2*2+1]);
            }
        }
}

// ---------------- kernel: combine slot pairs ----------------
__global__ void combine_kernel(float* __restrict__ out) {
    int idx = blockIdx.x * blockDim.x + threadIdx.x;
    if (idx >= T_TOK * H_DIM / 4) return;
    int t = idx >> 8;
    int h4 = idx & 255;
    const float4* a = (const float4*)(g_eo + (size_t)(2*t)   * H_DIM) + h4;
    const float4* b = (const float4*)(g_eo + (size_t)(2*t+1) * H_DIM) + h4;
    float4 va = *a, vb = *b, v;
    v.x = va.x + vb.x; v.y = va.y + vb.y; v.z = va.z + vb.z; v.w = va.w + vb.w;
    ((float4*)out)[idx] = v;
}

// ---------------- launch: conv_wdn forked BEFORE router (hides under router+gemm1) ----------------
extern "C" void kernel_launch(void* const* d_in, const int* in_sizes, int n_in,
                              void* d_out, int out_size) {
    const float* hidden = (const float*)d_in[0];
    const float* router = (const float*)d_in[1];
    const float* w_gu   = (const float*)d_in[2];
    const float* w_dn   = (const float*)d_in[3];
    float* out = (float*)d_out;

    static cudaStream_t s2;
    static cudaEvent_t evMid, evS2;
    static int inited = 0;
    if (!inited) {
        cudaStreamCreateWithFlags(&s2, cudaStreamNonBlocking);
        cudaEventCreateWithFlags(&evMid, cudaEventDisableTiming);
        cudaEventCreateWithFlags(&evS2, cudaEventDisableTiming);
        inited = 1;
    }

    // serial prologue (conv_x also zeroes counters; must precede router)
    convert_sel<<<(262144 + 255) / 256, 256>>>((const float4*)hidden, 0, 262144);
    convert_sel<<<(4194304 + 255) / 256, 256>>>((const float4*)w_gu, 1, 4194304);

    // fork BEFORE the router: conv_wdn (BW-bound) co-resides with the
    // latency-bound router (occ 21%, DRAM 4.6%) and then gemm1's head.
    cudaEventRecord(evMid, 0);
    cudaStreamWaitEvent(s2, evMid, 0);
    convert_sel<<<(2097152 + 255) / 256, 256, 0, s2>>>((const float4*)w_dn, 2, 2097152);
    cudaEventRecord(evS2, s2);

    dim3 rblk(32, 8);
    router_kernel<<<T_TOK / 8, rblk>>>(hidden, router);

    gemm1_kernel<<<dim3(32, 16, 16), 256>>>();

    // join before gemm2
    cudaStreamWaitEvent(0, evS2, 0);
    gemm2_kernel<<<dim3(32, 16, 8), 256>>>();

    combine_kernel<<<(T_TOK * H_DIM / 4 + 255) / 256, 256>>>(out);
}

// round 16
// speedup vs baseline: 1.0366x; 1.0366x over previous
#include <cuda_runtime.h>
#include <cuda_bf16.h>
#include <math.h>
#include <stdint.h>

#define T_TOK   2048
#define H_DIM   1024
#define N_EXP   16
#define F_DIM   1024
#define N_SLOTS 4096

// ---------------- device scratch (no allocations allowed) ----------------
__device__ __nv_bfloat16 g_xhi[(size_t)T_TOK * H_DIM];
__device__ __nv_bfloat16 g_xlo[(size_t)T_TOK * H_DIM];
__device__ __nv_bfloat16 g_guh[(size_t)N_EXP * H_DIM * 2048];
__device__ __nv_bfloat16 g_gul[(size_t)N_EXP * H_DIM * 2048];
__device__ __nv_bfloat16 g_dnh[(size_t)N_EXP * F_DIM * H_DIM];
__device__ __nv_bfloat16 g_dnl[(size_t)N_EXP * F_DIM * H_DIM];
__device__ __nv_bfloat16 g_hhi[(size_t)N_SLOTS * F_DIM];
__device__ __nv_bfloat16 g_hlo[(size_t)N_SLOTS * F_DIM];
__device__ int   g_cnt[N_EXP];
__device__ int   g_slots[N_EXP * N_SLOTS];
__device__ float g_w[N_SLOTS];

// ---------------- helpers ----------------
__device__ __forceinline__ uint32_t smem_u32(const void* p) {
    uint32_t a;
    asm("{ .reg .u64 t; cvta.to.shared.u64 t, %1; cvt.u32.u64 %0, t; }" : "=r"(a) : "l"(p));
    return a;
}
#define SW128(o) ((o) ^ (((o) >> 3) & 0x70))
#define SW64(o)  ((o) ^ (((o) >> 3) & 0x30))

__device__ __forceinline__ uint32_t pack2(__nv_bfloat16 a, __nv_bfloat16 b) {
    return (uint32_t)__bfloat16_as_ushort(a) | ((uint32_t)__bfloat16_as_ushort(b) << 16);
}
__device__ __forceinline__ void split1(float v, __nv_bfloat16& h, __nv_bfloat16& l) {
    h = __float2bfloat16(v);
    l = __float2bfloat16(v - __bfloat162float(h));
}

__device__ __forceinline__ void cpa16(uint32_t dst, const void* src, int sz) {
    asm volatile("cp.async.cg.shared.global [%0], [%1], 16, %2;"
        :: "r"(dst), "l"(src), "r"(sz) : "memory");
}
#define CP_COMMIT() asm volatile("cp.async.commit_group;" ::: "memory")
#define CP_WAIT(n)  asm volatile("cp.async.wait_group %0;" :: "n"(n) : "memory")

__device__ __forceinline__ void ldsm4(uint32_t (&r)[4], uint32_t addr) {
    asm volatile("ldmatrix.sync.aligned.m8n8.x4.shared.b16 {%0,%1,%2,%3}, [%4];"
        : "=r"(r[0]), "=r"(r[1]), "=r"(r[2]), "=r"(r[3]) : "r"(addr));
}
__device__ __forceinline__ void ldsm4t(uint32_t (&r)[4], uint32_t addr) {
    asm volatile("ldmatrix.sync.aligned.m8n8.x4.trans.shared.b16 {%0,%1,%2,%3}, [%4];"
        : "=r"(r[0]), "=r"(r[1]), "=r"(r[2]), "=r"(r[3]) : "r"(addr));
}
__device__ __forceinline__ void mma16816(float (&d)[4], const uint32_t (&a)[4],
                                         uint32_t b0, uint32_t b1) {
    asm volatile("mma.sync.aligned.m16n8k16.row.col.f32.bf16.bf16.f32 "
        "{%0,%1,%2,%3},{%4,%5,%6,%7},{%8,%9},{%0,%1,%2,%3};"
        : "+f"(d[0]), "+f"(d[1]), "+f"(d[2]), "+f"(d[3])
        : "r"(a[0]), "r"(a[1]), "r"(a[2]), "r"(a[3]), "r"(b0), "r"(b1));
}

// ---------------- kernel: zero the output buffer ----------------
__global__ void zero_out_kernel(float4* __restrict__ out) {
    int i = blockIdx.x * blockDim.x + threadIdx.x;
    if (i < T_TOK * H_DIM / 4) out[i] = make_float4(0.f, 0.f, 0.f, 0.f);
}

// ---------------- kernel: fp32 -> bf16 hi/lo plane split (vectorized 2x) ----------------
// sel==0 additionally zeroes the expert counters (block 0).
__global__ void convert_sel(const float4* __restrict__ src, int sel, int n8) {
    if (sel == 0 && blockIdx.x == 0 && threadIdx.x < N_EXP) g_cnt[threadIdx.x] = 0;
    int i = blockIdx.x * blockDim.x + threadIdx.x;   // uint4 (8-element) index
    if (i >= n8) return;
    uint4* hi; uint4* lo;
    if (sel == 0)      { hi = (uint4*)g_xhi; lo = (uint4*)g_xlo; }
    else if (sel == 1) { hi = (uint4*)g_guh; lo = (uint4*)g_gul; }
    else               { hi = (uint4*)g_dnh; lo = (uint4*)g_dnl; }
    float4 v0 = src[2 * i], v1 = src[2 * i + 1];
    __nv_bfloat16 h0,h1,h2,h3,h4,h5,h6,h7,l0,l1,l2,l3,l4,l5,l6,l7;
    split1(v0.x,h0,l0); split1(v0.y,h1,l1); split1(v0.z,h2,l2); split1(v0.w,h3,l3);
    split1(v1.x,h4,l4); split1(v1.y,h5,l5); split1(v1.z,h6,l6); split1(v1.w,h7,l7);
    hi[i] = make_uint4(pack2(h0,h1), pack2(h2,h3), pack2(h4,h5), pack2(h6,h7));
    lo[i] = make_uint4(pack2(l0,l1), pack2(l2,l3), pack2(l4,l5), pack2(l6,l7));
}

// ---------------- kernel: router (champion version) ----------------
__global__ void router_kernel(const float* __restrict__ x, const float* __restrict__ rw) {
    int t = blockIdx.x * blockDim.y + threadIdx.y;
    if (t >= T_TOK) return;
    int lane = threadIdx.x;
    float acc[N_EXP];
#pragma unroll
    for (int e = 0; e < N_EXP; e++) acc[e] = 0.f;
    const float* xrow = x + (size_t)t * H_DIM;
    for (int h = lane; h < H_DIM; h += 32) {
        float xv = xrow[h];
        const float4* r4 = (const float4*)(rw + (size_t)h * N_EXP);
#pragma unroll
        for (int q = 0; q < 4; q++) {
            float4 v = r4[q];
            acc[q*4+0] += xv*v.x; acc[q*4+1] += xv*v.y;
            acc[q*4+2] += xv*v.z; acc[q*4+3] += xv*v.w;
        }
    }
#pragma unroll
    for (int e = 0; e < N_EXP; e++)
#pragma unroll
        for (int off = 16; off > 0; off >>= 1)
            acc[e] += __shfl_down_sync(0xffffffffu, acc[e], off);
    if (lane == 0) {
        int i0 = -1, i1 = -1; float v0 = -INFINITY, v1 = -INFINITY;
#pragma unroll
        for (int e = 0; e < N_EXP; e++) {
            float v = acc[e];
            if (v > v0) { v1 = v0; i1 = i0; v0 = v; i0 = e; }
            else if (v > v1) { v1 = v; i1 = e; }
        }
        float w0 = 1.f / (1.f + expf(v1 - v0));
        int p0 = atomicAdd(&g_cnt[i0], 1);
        g_slots[i0 * N_SLOTS + p0] = 2*t;     g_w[2*t]   = w0;
        int p1 = atomicAdd(&g_cnt[i1], 1);
        g_slots[i1 * N_SLOTS + p1] = 2*t+1;   g_w[2*t+1] = 1.f - w0;
    }
}

// ---------------- 2-stage mainloop: 128x128 tile, K=1024, chunk 16 ----------------
__device__ __forceinline__ void stage_chunk(
    int c, uint32_t dA, uint32_t dB, const int* rows, int shift,
    const __nv_bfloat16* __restrict__ Ahi, const __nv_bfloat16* __restrict__ Alo,
    const __nv_bfloat16* __restrict__ Bhi, const __nv_bfloat16* __restrict__ Blo,
    size_t bbase, int bstride, int bnh)
{
    int tid = threadIdx.x;
#pragma unroll
    for (int it = 0; it < 2; it++) {
        int i = tid + it * 256;
        int m = i >> 2, ch = i & 3, p = ch >> 1, kq = ch & 1;
        int s = rows[m];
        const __nv_bfloat16* base = p ? Alo : Ahi;
        int sr = (s < 0) ? 0 : (s >> shift);
        const __nv_bfloat16* sp = base + ((size_t)sr * 1024 + c * 16 + kq * 8);
        cpa16(dA + SW64((uint32_t)(m * 64 + ch * 16)), sp, (s >= 0) ? 16 : 0);
    }
#pragma unroll
    for (int it = 0; it < 2; it++) {
        int i = tid + it * 256;
        int p = i >> 8, r = i & 255, nh = r >> 7, rr = r & 127, k = rr >> 3, nc = rr & 7;
        const __nv_bfloat16* base = p ? Blo : Bhi;
        const __nv_bfloat16* sp = base + (bbase + (size_t)(c * 16 + k) * bstride + nh * bnh + nc * 8);
        cpa16(dB + SW128((uint32_t)(p * 4096 + nh * 2048 + k * 128 + nc * 16)), sp, 16);
    }
}

__device__ __forceinline__ void gemm_loop(
    float (&acc)[2][8][4], char* smA, char* smB, const int* rows, int shift,
    const __nv_bfloat16* __restrict__ Ahi, const __nv_bfloat16* __restrict__ Alo,
    const __nv_bfloat16* __restrict__ Bhi, const __nv_bfloat16* __restrict__ Blo,
    size_t bbase, int bstride, int bnh)
{
    int lane = threadIdx.x & 31, wid = threadIdx.x >> 5;
    int wm = wid & 3, wn = wid >> 2;
    uint32_t aA = smem_u32(smA), aB = smem_u32(smB);

    stage_chunk(0, aA, aB, rows, shift, Ahi, Alo, Bhi, Blo, bbase, bstride, bnh);
    CP_COMMIT();

    for (int c = 0; c < 64; c++) {
        if (c < 63) {
            stage_chunk(c + 1, aA + ((c + 1) & 1) * 8192, aB + ((c + 1) & 1) * 8192,
                        rows, shift, Ahi, Alo, Bhi, Blo, bbase, bstride, bnh);
            CP_COMMIT();
            CP_WAIT(1);
        } else {
            CP_WAIT(0);
        }
        __syncthreads();
        uint32_t bA = aA + (c & 1) * 8192, bB = aB + (c & 1) * 8192;
        uint32_t ah[2][4], al[2][4], bhf[4][4], blf[4][4];
#pragma unroll
        for (int mf = 0; mf < 2; mf++) {
            int row = wm * 32 + mf * 16 + (lane & 15);
            int cb = (lane >> 4) * 16;
            ldsm4(ah[mf], bA + SW64((uint32_t)(row * 64 + cb)));
            ldsm4(al[mf], bA + SW64((uint32_t)(row * 64 + 32 + cb)));
        }
#pragma unroll
        for (int g = 0; g < 4; g++) {
            uint32_t co = wn * 2048 + (lane & 15) * 128 + (g * 16 + (lane >> 4) * 8) * 2;
            ldsm4t(bhf[g], bB + SW128(co));
            ldsm4t(blf[g], bB + SW128(4096 + co));
        }
#pragma unroll
        for (int mf = 0; mf < 2; mf++)
#pragma unroll
            for (int g = 0; g < 4; g++) {
                mma16816(acc[mf][2*g],   ah[mf], bhf[g][0], bhf[g][1]);
                mma16816(acc[mf][2*g+1], ah[mf], bhf[g][2], bhf[g][3]);
                mma16816(acc[mf][2*g],   ah[mf], blf[g][0], blf[g][1]);
                mma16816(acc[mf][2*g+1], ah[mf], blf[g][2], blf[g][3]);
                mma16816(acc[mf][2*g],   al[mf], bhf[g][0], bhf[g][1]);
                mma16816(acc[mf][2*g+1], al[mf], bhf[g][2], bhf[g][3]);
            }
        __syncthreads();
    }
}

// ---------------- kernel: gate_up GEMM + fused SiLU ----------------
// grid (32 m-tiles, 16 experts, 16 f-tiles): 64 f per tile (gate j*64.., up 1024+j*64..)
__global__ __launch_bounds__(256) void gemm1_kernel() {
    __shared__ int rows[128];
    __shared__ __align__(128) char smem_all[35328];
    int e = blockIdx.y, m0 = blockIdx.x * 128, j = blockIdx.z;
    int cnt = g_cnt[e];
    if (m0 >= cnt) return;
    int tid = threadIdx.x, lane = tid & 31, wid = tid >> 5, wm = wid & 3, wn = wid >> 2;
    if (tid < 128) rows[tid] = (m0 + tid < cnt) ? g_slots[e * N_SLOTS + m0 + tid] : -1;
    __syncthreads();

    float acc[2][8][4] = {};
    gemm_loop(acc, smem_all, smem_all + 16384, rows, 1,
              g_xhi, g_xlo, g_guh, g_gul,
              (size_t)e * H_DIM * 2048 + (size_t)j * 64, 2048, 1024);

    // epilogue: exchange up half through SMEM, fuse SiLU, write bf16 hi/lo act
    float* up_sm = (float*)smem_all;   // [128][68]
    if (wn == 1) {
#pragma unroll
        for (int mf = 0; mf < 2; mf++)
#pragma unroll
            for (int nf = 0; nf < 8; nf++) {
                int f = nf * 8 + (lane & 3) * 2;
                int m = wm * 32 + mf * 16 + (lane >> 2);
                up_sm[m * 68 + f]           = acc[mf][nf][0];
                up_sm[m * 68 + f + 1]       = acc[mf][nf][1];
                up_sm[(m + 8) * 68 + f]     = acc[mf][nf][2];
                up_sm[(m + 8) * 68 + f + 1] = acc[mf][nf][3];
            }
    }
    __syncthreads();
    if (wn == 0) {
#pragma unroll
        for (int mf = 0; mf < 2; mf++)
#pragma unroll
            for (int nf = 0; nf < 8; nf++) {
                int f = nf * 8 + (lane & 3) * 2;
                int mb = wm * 32 + mf * 16 + (lane >> 2);
#pragma unroll
                for (int h2 = 0; h2 < 2; h2++) {
                    int m = mb + h2 * 8;
                    int s = rows[m];
                    if (s < 0) continue;
                    float gg0 = acc[mf][nf][h2*2], gg1 = acc[mf][nf][h2*2+1];
                    float u0 = up_sm[m*68 + f], u1 = up_sm[m*68 + f + 1];
                    float x0 = gg0 / (1.f + expf(-gg0)) * u0;
                    float x1 = gg1 / (1.f + expf(-gg1)) * u1;
                    __nv_bfloat16 h0,h1,l0,l1;
                    split1(x0,h0,l0); split1(x1,h1,l1);
                    size_t o = (size_t)s * F_DIM + j * 64 + f;
                    *(uint32_t*)(g_hhi + o) = pack2(h0,h1);
                    *(uint32_t*)(g_hlo + o) = pack2(l0,l1);
                }
            }
    }
}

// ---------------- kernel: down GEMM (+routing weight, fused combine via atomics) ----------------
// grid (32 m-tiles, 16 experts, 8 h-tiles)
__global__ __launch_bounds__(256) void gemm2_kernel(float* __restrict__ out) {
    __shared__ int rows[128];
    __shared__ __align__(128) char smem_all[32768];
    int e = blockIdx.y, m0 = blockIdx.x * 128, n0 = blockIdx.z * 128;
    int cnt = g_cnt[e];
    if (m0 >= cnt) return;
    int tid = threadIdx.x, lane = tid & 31, wid = tid >> 5, wm = wid & 3, wn = wid >> 2;
    if (tid < 128) rows[tid] = (m0 + tid < cnt) ? g_slots[e * N_SLOTS + m0 + tid] : -1;
    __syncthreads();

    float acc[2][8][4] = {};
    gemm_loop(acc, smem_all, smem_all + 16384, rows, 0,
              g_hhi, g_hlo, g_dnh, g_dnl,
              (size_t)e * F_DIM * H_DIM + (size_t)n0, 1024, 64);

    // epilogue: weighted atomic accumulate straight into out[t, n].
    // Each element gets exactly 2 contributions (one per selected expert slot);
    // fp32 add is commutative, initial value is exact 0 -> bitwise deterministic.
#pragma unroll
    for (int mf = 0; mf < 2; mf++)
#pragma unroll
        for (int nf = 0; nf < 8; nf++) {
            int n = n0 + wn * 64 + nf * 8 + (lane & 3) * 2;
            int mb = wm * 32 + mf * 16 + (lane >> 2);
#pragma unroll
            for (int h2 = 0; h2 < 2; h2++) {
                int m = mb + h2 * 8;
                int s = rows[m];
                if (s < 0) continue;
                float w = g_w[s];
                float* op = out + (size_t)(s >> 1) * H_DIM + n;
                atomicAdd(op,     w * acc[mf][nf][h2*2]);
                atomicAdd(op + 1, w * acc[mf][nf][h2*2+1]);
            }
        }
}

// ---------------- launch ----------------
extern "C" void kernel_launch(void* const* d_in, const int* in_sizes, int n_in,
                              void* d_out, int out_size) {
    const float* hidden = (const float*)d_in[0];
    const float* router = (const float*)d_in[1];
    const float* w_gu   = (const float*)d_in[2];
    const float* w_dn   = (const float*)d_in[3];
    float* out = (float*)d_out;

    static cudaStream_t s2;
    static cudaEvent_t evMid, evS2;
    static int inited = 0;
    if (!inited) {
        cudaStreamCreateWithFlags(&s2, cudaStreamNonBlocking);
        cudaEventCreateWithFlags(&evMid, cudaEventDisableTiming);
        cudaEventCreateWithFlags(&evS2, cudaEventDisableTiming);
        inited = 1;
    }

    // serial prologue (zero out first; conv_x also zeroes counters; must precede router)
    zero_out_kernel<<<(T_TOK * H_DIM / 4 + 255) / 256, 256>>>((float4*)out);
    convert_sel<<<(262144 + 255) / 256, 256>>>((const float4*)hidden, 0, 262144);
    convert_sel<<<(4194304 + 255) / 256, 256>>>((const float4*)w_gu, 1, 4194304);
    dim3 rblk(32, 8);
    router_kernel<<<T_TOK / 8, rblk>>>(hidden, router);

    // fork (R14 placement): conv_wdn concurrent with gemm1
    cudaEventRecord(evMid, 0);
    cudaStreamWaitEvent(s2, evMid, 0);
    convert_sel<<<(2097152 + 255) / 256, 256, 0, s2>>>((const float4*)w_dn, 2, 2097152);
    cudaEventRecord(evS2, s2);

    gemm1_kernel<<<dim3(32, 16, 16), 256>>>();

    // join before gemm2
    cudaStreamWaitEvent(0, evS2, 0);
    gemm2_kernel<<<dim3(32, 16, 8), 256>>>(out);
}